// round 17
// baseline (speedup 1.0000x reference)
#include <cuda_runtime.h>
#include <cstdint>
#include <math.h>

#define BB 16
#define NN 1024
#define HH 256
#define FIN 64

// ---------------- scratch ----------------
__device__ float g_x[BB*NN*HH];
__device__ float g_h[BB*NN*HH];
__device__ float g_s1[BB*NN];
__device__ float g_s2[BB*NN];

__device__ __forceinline__ uint32_t to_tf32(float x) {
    uint32_t u;
    asm("cvt.rna.tf32.f32 %0, %1;" : "=r"(u) : "f"(x));
    return u;
}
__device__ __forceinline__ void mma_tf32(float* c, const uint32_t* a, const uint32_t* bf) {
    asm volatile("mma.sync.aligned.m16n8k8.row.col.f32.tf32.tf32.f32 "
        "{%0,%1,%2,%3}, {%4,%5,%6,%7}, {%8,%9}, {%0,%1,%2,%3};"
        : "+f"(c[0]), "+f"(c[1]), "+f"(c[2]), "+f"(c[3])
        : "r"(a[0]), "r"(a[1]), "r"(a[2]), "r"(a[3]), "r"(bf[0]), "r"(bf[1]));
}

// =====================================================================
// tf32 mma GEMM (512 thr). Fragment-major double-buffered A staging:
// warp w produces fragments (m = w>>1, kk = 2*(w&1)+f), thread (g,tid4)
// owns the exact 4-value mma A-fragment -> 1 STS.128; consumer does
// 1 LDS.128 per fragment. One barrier per k-tile.
// =====================================================================
template<int K, bool BIAS, bool SDOT>
__global__ void __launch_bounds__(512, 1)
mm_mma_k(const float* __restrict__ x, const float* __restrict__ W,
         const float* __restrict__ bias,
         const float* __restrict__ a1, const float* __restrict__ a2,
         float* __restrict__ outh, float* __restrict__ s1, float* __restrict__ s2) {
    __shared__ uint4 Ps[2][1024];     // [buf][(m*4+kk)*32 + lane]
    __shared__ float s1sh[128];
    __shared__ float s2sh[128];

    const int t = threadIdx.x;
    const int wid = t >> 5, lane = t & 31;
    const int g = lane >> 2, tid4 = lane & 3;
    const int r0 = blockIdx.x * 128;

    if (SDOT && t < 128) { s1sh[t] = 0.f; s2sh[t] = 0.f; }

    // producer role
    const int pm  = wid >> 1;
    const int pk0 = (wid & 1) * 2;
    const int i0 = pm * 16 + g, i1 = i0 + 8;
    const float* xA = x + (size_t)(r0 + i0) * K;
    const float* xB = x + (size_t)(r0 + i1) * K;
    // consumer role
    const float* Wc = W + wid * 16;

    float acc[8][2][4];
#pragma unroll
    for (int m = 0; m < 8; m++)
#pragma unroll
        for (int n = 0; n < 2; n++)
#pragma unroll
            for (int e = 0; e < 4; e++) acc[m][n][e] = 0.f;

    float xw[2][4];
    auto LOADX = [&](int k0) {
#pragma unroll
        for (int f = 0; f < 2; f++) {
            const int c0 = k0 + (pk0 + f) * 8 + tid4;
            xw[f][0] = xA[c0];  xw[f][1] = xB[c0];
            xw[f][2] = xA[c0+4]; xw[f][3] = xB[c0+4];
        }
    };
    auto PRODUCE = [&](int buf) {
#pragma unroll
        for (int f = 0; f < 2; f++) {
            Ps[buf][(pm * 4 + pk0 + f) * 32 + lane] =
                make_uint4(to_tf32(xw[f][0]), to_tf32(xw[f][1]),
                           to_tf32(xw[f][2]), to_tf32(xw[f][3]));
        }
    };

    const int NKT = K / 32;
    LOADX(0);
    PRODUCE(0);
    if (NKT > 1) LOADX(32);
    __syncthreads();

    for (int kt = 0; kt < NKT; kt++) {
        const int k0 = kt * 32;
        const int buf = kt & 1;
        if (kt + 1 < NKT) PRODUCE(buf ^ 1);
        if (kt + 2 < NKT) LOADX(k0 + 64);

        uint32_t bc[2][2], bn[2][2];
#pragma unroll
        for (int n = 0; n < 2; n++) {
            bc[n][0] = to_tf32(Wc[(size_t)(k0 + tid4) * HH + n * 8 + g]);
            bc[n][1] = to_tf32(Wc[(size_t)(k0 + tid4 + 4) * HH + n * 8 + g]);
        }
#pragma unroll
        for (int kk = 0; kk < 4; kk++) {
            if (kk < 3) {
                const int kr = k0 + (kk + 1) * 8;
#pragma unroll
                for (int n = 0; n < 2; n++) {
                    bn[n][0] = to_tf32(Wc[(size_t)(kr + tid4) * HH + n * 8 + g]);
                    bn[n][1] = to_tf32(Wc[(size_t)(kr + tid4 + 4) * HH + n * 8 + g]);
                }
            }
#pragma unroll
            for (int m = 0; m < 8; m++) {
                uint4 a4 = Ps[buf][(m * 4 + kk) * 32 + lane];
                mma_tf32(acc[m][0], reinterpret_cast<const uint32_t*>(&a4), bc[0]);
                mma_tf32(acc[m][1], reinterpret_cast<const uint32_t*>(&a4), bc[1]);
            }
#pragma unroll
            for (int n = 0; n < 2; n++) { bc[n][0] = bn[n][0]; bc[n][1] = bn[n][1]; }
        }
        __syncthreads();
    }

    // epilogue
    float2 bb[2], a1v[2], a2v[2];
#pragma unroll
    for (int n = 0; n < 2; n++) {
        const int c = wid * 16 + n * 8 + tid4 * 2;
        if (BIAS) bb[n] = *reinterpret_cast<const float2*>(bias + c);
        if (SDOT) {
            a1v[n] = *reinterpret_cast<const float2*>(a1 + c);
            a2v[n] = *reinterpret_cast<const float2*>(a2 + c);
        }
    }
    float* ob = outh + (size_t)r0 * HH + wid * 16;
#pragma unroll
    for (int m = 0; m < 8; m++) {
        const int rA = m * 16 + g, rB = rA + 8;
        float d1A = 0.f, d2A = 0.f, d1B = 0.f, d2B = 0.f;
#pragma unroll
        for (int n = 0; n < 2; n++) {
            const int c = n * 8 + tid4 * 2;
            float vA0 = acc[m][n][0] + (BIAS ? bb[n].x : 0.f);
            float vA1 = acc[m][n][1] + (BIAS ? bb[n].y : 0.f);
            float vB0 = acc[m][n][2] + (BIAS ? bb[n].x : 0.f);
            float vB1 = acc[m][n][3] + (BIAS ? bb[n].y : 0.f);
            *reinterpret_cast<float2*>(ob + (size_t)rA * HH + c) = make_float2(vA0, vA1);
            *reinterpret_cast<float2*>(ob + (size_t)rB * HH + c) = make_float2(vB0, vB1);
            if (SDOT) {
                d1A = fmaf(vA0, a1v[n].x, fmaf(vA1, a1v[n].y, d1A));
                d2A = fmaf(vA0, a2v[n].x, fmaf(vA1, a2v[n].y, d2A));
                d1B = fmaf(vB0, a1v[n].x, fmaf(vB1, a1v[n].y, d1B));
                d2B = fmaf(vB0, a2v[n].x, fmaf(vB1, a2v[n].y, d2B));
            }
        }
        if (SDOT) {
#pragma unroll
            for (int off = 1; off < 4; off <<= 1) {
                d1A += __shfl_xor_sync(~0u, d1A, off);
                d2A += __shfl_xor_sync(~0u, d2A, off);
                d1B += __shfl_xor_sync(~0u, d1B, off);
                d2B += __shfl_xor_sync(~0u, d2B, off);
            }
            if (tid4 == 0) {
                atomicAdd(&s1sh[rA], d1A);
                atomicAdd(&s2sh[rA], d2A);
                atomicAdd(&s1sh[rB], d1B);
                atomicAdd(&s2sh[rB], d2B);
            }
        }
    }
    if (SDOT) {
        __syncthreads();
        if (t < 128) { s1[r0 + t] = s1sh[t]; s2[r0 + t] = s2sh[t]; }
    }
}

// =====================================================================
// tf32 mma fused attention (512 thr), fragment-major double-buffered P,
// __expf producer, register row-sums.
// =====================================================================
__global__ void __launch_bounds__(512, 1)
attn_mma_k(const float* __restrict__ h, const float* __restrict__ adj,
           const float* __restrict__ s1, const float* __restrict__ s2,
           float* __restrict__ out) {
    __shared__ uint4 Ps[2][1024];
    __shared__ float s2f[NN];
    __shared__ float s_m[128];
    __shared__ float s_s1r[128];
    __shared__ float s_rs[128];
    __shared__ float s_inv[128];
    __shared__ float s_red[16];

    const int t = threadIdx.x;
    const int wid = t >> 5, lane = t & 31;
    const int g = lane >> 2, tid4 = lane & 3;
    const int b = blockIdx.y;
    const int r0 = blockIdx.x * 128;

    if (t < 128) s_rs[t] = 0.f;

    // s2 -> smem + block max
    const float* s2b = s2 + b * NN;
    float mx = -3.4e38f;
#pragma unroll
    for (int q = 0; q < 2; q++) {
        float v = s2b[t + q * 512];
        s2f[t + q * 512] = v;
        mx = fmaxf(mx, v);
    }
#pragma unroll
    for (int off = 16; off; off >>= 1) mx = fmaxf(mx, __shfl_xor_sync(~0u, mx, off));
    if (lane == 0) s_red[wid] = mx;
    __syncthreads();
    if (t == 0) {
        float m = s_red[0];
#pragma unroll
        for (int w = 1; w < 16; w++) m = fmaxf(m, s_red[w]);
        s_red[0] = m;
    }
    __syncthreads();
    const float s2max = s_red[0];
    if (t < 128) {
        float sv = s1[b * NN + r0 + t];
        s_s1r[t] = sv;
        float z = sv + s2max;
        s_m[t] = fmaxf(z, 0.2f * z);
    }
    __syncthreads();

    // producer role: warp -> (mtile, kk pair); thread -> fragment (g, tid4)
    const int pm  = wid >> 1;
    const int pk0 = (wid & 1) * 2;
    const int i0 = pm * 16 + g, i1 = i0 + 8;
    const float s1A = s_s1r[i0], s1B = s_s1r[i1];
    const float mA = s_m[i0], mB = s_m[i1];
    float rsA = 0.f, rsB = 0.f;
    const float* adjA = adj + (size_t)(b * NN + r0 + i0) * NN;
    const float* adjB = adj + (size_t)(b * NN + r0 + i1) * NN;
    // consumer role: warp owns 16 output cols
    const float* hw = h + (size_t)b * NN * HH + wid * 16;

    float acc[8][2][4];
#pragma unroll
    for (int m = 0; m < 8; m++)
#pragma unroll
        for (int n = 0; n < 2; n++)
#pragma unroll
            for (int e = 0; e < 4; e++) acc[m][n][e] = 0.f;

    float aw[2][4];
    auto LOADADJ = [&](int j0) {
#pragma unroll
        for (int f = 0; f < 2; f++) {
            const int c0 = j0 + (pk0 + f) * 8 + tid4;
            aw[f][0] = adjA[c0];   aw[f][1] = adjB[c0];
            aw[f][2] = adjA[c0+4]; aw[f][3] = adjB[c0+4];
        }
    };
    auto PRODUCE = [&](int j0, int buf) {
#pragma unroll
        for (int f = 0; f < 2; f++) {
            const int c0 = j0 + (pk0 + f) * 8 + tid4;
            float sa = s2f[c0], sb = s2f[c0 + 4];
            float zA0 = s1A + sa, zB0 = s1B + sa, zA1 = s1A + sb, zB1 = s1B + sb;
            float p0 = aw[f][0] * __expf(fmaxf(zA0, 0.2f * zA0) - mA);
            float p1 = aw[f][1] * __expf(fmaxf(zB0, 0.2f * zB0) - mB);
            float p2 = aw[f][2] * __expf(fmaxf(zA1, 0.2f * zA1) - mA);
            float p3 = aw[f][3] * __expf(fmaxf(zB1, 0.2f * zB1) - mB);
            rsA += p0 + p2;
            rsB += p1 + p3;
            Ps[buf][(pm * 4 + pk0 + f) * 32 + lane] =
                make_uint4(to_tf32(p0), to_tf32(p1), to_tf32(p2), to_tf32(p3));
        }
    };

    LOADADJ(0);
    PRODUCE(0, 0);
    LOADADJ(32);
    __syncthreads();

    for (int tile = 0; tile < 32; tile++) {
        const int j0 = tile * 32;
        const int buf = tile & 1;
        if (tile + 1 < 32) PRODUCE(j0 + 32, buf ^ 1);
        if (tile + 2 < 32) LOADADJ(j0 + 64);

        uint32_t bc[2][2], bn[2][2];
#pragma unroll
        for (int n = 0; n < 2; n++) {
            bc[n][0] = to_tf32(hw[(size_t)(j0 + tid4) * HH + n * 8 + g]);
            bc[n][1] = to_tf32(hw[(size_t)(j0 + tid4 + 4) * HH + n * 8 + g]);
        }
#pragma unroll
        for (int kk = 0; kk < 4; kk++) {
            if (kk < 3) {
                const int jr = j0 + (kk + 1) * 8;
#pragma unroll
                for (int n = 0; n < 2; n++) {
                    bn[n][0] = to_tf32(hw[(size_t)(jr + tid4) * HH + n * 8 + g]);
                    bn[n][1] = to_tf32(hw[(size_t)(jr + tid4 + 4) * HH + n * 8 + g]);
                }
            }
#pragma unroll
            for (int m = 0; m < 8; m++) {
                uint4 a4 = Ps[buf][(m * 4 + kk) * 32 + lane];
                mma_tf32(acc[m][0], reinterpret_cast<const uint32_t*>(&a4), bc[0]);
                mma_tf32(acc[m][1], reinterpret_cast<const uint32_t*>(&a4), bc[1]);
            }
#pragma unroll
            for (int n = 0; n < 2; n++) { bc[n][0] = bn[n][0]; bc[n][1] = bn[n][1]; }
        }
        __syncthreads();
    }

    // row-sum reduction: quad shuffle then one shared atomic per row
#pragma unroll
    for (int off = 1; off < 4; off <<= 1) {
        rsA += __shfl_xor_sync(~0u, rsA, off);
        rsB += __shfl_xor_sync(~0u, rsB, off);
    }
    if (tid4 == 0) {
        atomicAdd(&s_rs[i0], rsA);
        atomicAdd(&s_rs[i1], rsB);
    }
    __syncthreads();
    if (t < 128) s_inv[t] = 1.f / s_rs[t];
    __syncthreads();

    float* ob = out + ((size_t)(b * NN + r0)) * HH + wid * 16;
#pragma unroll
    for (int m = 0; m < 8; m++) {
        const int rA = m * 16 + g, rB = rA + 8;
        const float invA = s_inv[rA], invB = s_inv[rB];
#pragma unroll
        for (int n = 0; n < 2; n++) {
            const int c = n * 8 + tid4 * 2;
            float2 vA = make_float2(fmaxf(acc[m][n][0] * invA, 0.f),
                                    fmaxf(acc[m][n][1] * invA, 0.f));
            float2 vB = make_float2(fmaxf(acc[m][n][2] * invB, 0.f),
                                    fmaxf(acc[m][n][3] * invB, 0.f));
            *reinterpret_cast<float2*>(ob + (size_t)rA * HH + c) = vA;
            *reinterpret_cast<float2*>(ob + (size_t)rB * HH + c) = vB;
        }
    }
}

// ---------------- pooling + MLP ----------------
__global__ void pool_k(const float* __restrict__ x, const float* __restrict__ W1,
                       const float* __restrict__ b1, const float* __restrict__ W2,
                       const float* __restrict__ b2, float* __restrict__ g) {
    __shared__ float g0s[HH];
    __shared__ float g1s[HH];
    const int t = threadIdx.x, b = blockIdx.x;
    const float* xb = x + b * NN * HH;
    float sum = 0.f, mx = -3.4e38f;
    for (int n = 0; n < NN; n++) {
        float v = xb[n * HH + t];
        sum += v;
        mx = fmaxf(mx, v);
    }
    g0s[t] = sum * (1.0f / NN) + mx;
    __syncthreads();
    float acc = b1[t];
#pragma unroll 8
    for (int k = 0; k < HH; k++) acc = fmaf(g0s[k], W1[k * HH + t], acc);
    g1s[t] = fmaxf(acc, 0.f);
    __syncthreads();
    float acc2 = b2[t];
#pragma unroll 8
    for (int k = 0; k < HH; k++) acc2 = fmaf(g1s[k], W2[k * HH + t], acc2);
    g[b * HH + t] = acc2;
}

extern "C" void kernel_launch(void* const* d_in, const int* in_sizes, int n_in,
                              void* d_out, int out_size) {
    const float* nf   = (const float*)d_in[0];
    const float* adj  = (const float*)d_in[1];
    const float* embW = (const float*)d_in[2];
    const float* embB = (const float*)d_in[3];
    const float* W0   = (const float*)d_in[4];
    const float* a1_0 = (const float*)d_in[5];
    const float* a2_0 = (const float*)d_in[6];
    const float* W1   = (const float*)d_in[7];
    const float* a1_1 = (const float*)d_in[8];
    const float* a2_1 = (const float*)d_in[9];
    const float* gW1  = (const float*)d_in[10];
    const float* gb1  = (const float*)d_in[11];
    const float* gW2  = (const float*)d_in[12];
    const float* gb2  = (const float*)d_in[13];
    float* out = (float*)d_out;

    float *xbuf, *hbuf, *s1, *s2;
    cudaGetSymbolAddress((void**)&xbuf, g_x);
    cudaGetSymbolAddress((void**)&hbuf, g_h);
    cudaGetSymbolAddress((void**)&s1, g_s1);
    cudaGetSymbolAddress((void**)&s2, g_s2);

    const int NB = BB * NN / 128;   // 128 blocks

    // embed: x = nf @ embW + embB
    mm_mma_k<FIN, true, false><<<NB, 512>>>(nf, embW, embB, nullptr, nullptr,
                                            xbuf, nullptr, nullptr);
    // layer 0: h = x @ W0, fused s1/s2
    mm_mma_k<HH, false, true><<<NB, 512>>>(xbuf, W0, nullptr, a1_0, a2_0,
                                           hbuf, s1, s2);
    attn_mma_k<<<dim3(NN / 128, BB), 512>>>(hbuf, adj, s1, s2, xbuf);
    // layer 1
    mm_mma_k<HH, false, true><<<NB, 512>>>(xbuf, W1, nullptr, a1_1, a2_1,
                                           hbuf, s1, s2);
    attn_mma_k<<<dim3(NN / 128, BB), 512>>>(hbuf, adj, s1, s2, out);

    pool_k<<<BB, 256>>>(out, gW1, gb1, gW2, gb2, out + BB * NN * HH);
}